// round 8
// baseline (speedup 1.0000x reference)
#include <cuda_runtime.h>

#define NN 100000
#define NE 1600000
#define NB_SCAN ((NN + 1023) / 1024)   // 98

__device__ int   g_cnt[NN];
__device__ int   g_off[NN + 1];
__device__ int   g_bsum[NB_SCAN];
__device__ int   g_fill[NN];
__device__ int   g_srcs[NE];
__device__ float g_dinv[NN];
__device__ __align__(16) float g_t[NN * 64];   // tt = dinv*(x@W1); later dinv*agg2 (gemm2 input)
__device__ __align__(16) float g_a[NN * 64];   // hh = dinv*relu(dinv*agg1 + b1)

__device__ __forceinline__ unsigned f2tf(float f) {
    unsigned u;
    asm("cvt.rna.tf32.f32 %0, %1;" : "=r"(u) : "f"(f));
    return u;
}

__device__ __forceinline__ void mma_tf32(float* d, const unsigned* a, unsigned b0, unsigned b1) {
    asm("mma.sync.aligned.m16n8k8.row.col.f32.tf32.tf32.f32 "
        "{%0,%1,%2,%3},{%4,%5,%6,%7},{%8,%9},{%0,%1,%2,%3};"
        : "+f"(d[0]), "+f"(d[1]), "+f"(d[2]), "+f"(d[3])
        : "r"(a[0]), "r"(a[1]), "r"(a[2]), "r"(a[3]), "r"(b0), "r"(b1));
}

__global__ void k_zero() {
    int i = blockIdx.x * 256 + threadIdx.x;
    if (i < NN) g_cnt[i] = 0;
}

__global__ void k_count(const int* __restrict__ dst) {
    int e = blockIdx.x * 256 + threadIdx.x;
    if (e < NE) atomicAdd(&g_cnt[dst[e]], 1);
}

// ---- 3-kernel exclusive prefix scan of g_cnt into g_off ----
__global__ __launch_bounds__(256) void k_scan1() {
    __shared__ int sh[256];
    int b = blockIdx.x, t = threadIdx.x;
    int base = b * 1024 + t * 4;
    int c0 = (base + 0 < NN) ? g_cnt[base + 0] : 0;
    int c1 = (base + 1 < NN) ? g_cnt[base + 1] : 0;
    int c2 = (base + 2 < NN) ? g_cnt[base + 2] : 0;
    int c3 = (base + 3 < NN) ? g_cnt[base + 3] : 0;
    int s = c0 + c1 + c2 + c3;
    sh[t] = s;
    __syncthreads();
    for (int ofs = 1; ofs < 256; ofs <<= 1) {
        int v = (t >= ofs) ? sh[t - ofs] : 0;
        __syncthreads();
        sh[t] += v;
        __syncthreads();
    }
    int excl = sh[t] - s;
    if (base + 0 < NN) g_off[base + 0] = excl;
    if (base + 1 < NN) g_off[base + 1] = excl + c0;
    if (base + 2 < NN) g_off[base + 2] = excl + c0 + c1;
    if (base + 3 < NN) g_off[base + 3] = excl + c0 + c1 + c2;
    if (t == 255) g_bsum[b] = sh[255];
}

// Parallel scan of the 98 block sums (was a 7.9us single-thread loop).
__global__ __launch_bounds__(128) void k_scan2() {
    __shared__ int sh[128];
    int t = threadIdx.x;
    int v = (t < NB_SCAN) ? g_bsum[t] : 0;
    sh[t] = v;
    __syncthreads();
    #pragma unroll
    for (int ofs = 1; ofs < 128; ofs <<= 1) {
        int u = (t >= ofs) ? sh[t - ofs] : 0;
        __syncthreads();
        sh[t] += u;
        __syncthreads();
    }
    if (t < NB_SCAN) g_bsum[t] = sh[t] - v;   // exclusive
    if (t == NB_SCAN - 1) g_off[NN] = sh[t];  // == NE
}

__global__ void k_scan3() {   // finalize offsets, init fill cursors, compute dinv
    int i = blockIdx.x * 256 + threadIdx.x;
    if (i < NN) {
        int o = g_off[i] + g_bsum[i >> 10];
        g_off[i] = o;
        g_fill[i] = o;
        g_dinv[i] = rsqrtf((float)(g_cnt[i] + 1));
    }
}

__global__ void k_fillcsr(const int* __restrict__ src, const int* __restrict__ dst) {
    int e = blockIdx.x * 256 + threadIdx.x;
    if (e < NE) {
        int pos = atomicAdd(&g_fill[dst[e]], 1);
        g_srcs[pos] = src[e];
    }
}

// tt = dinv * (x[N,128] @ W1[128,64]) via tf32 mma. 128 rows/block, 8 warps x 16 rows.
__global__ __launch_bounds__(256) void k_gemm1(const float* __restrict__ x,
                                               const float* __restrict__ W) {
    __shared__ unsigned xs[128 * 132];   // x tile, tf32, [row][k] pad 132
    __shared__ unsigned ws[128 * 72];    // W1, tf32, [k][n] pad 72
    int tid = threadIdx.x;
    int row0 = blockIdx.x * 128;
    const float4* x4 = (const float4*)x;
    const float4* W4 = (const float4*)W;

    #pragma unroll
    for (int i = tid; i < 2048; i += 256) {      // W1: 128x64 = 2048 float4
        int k = i >> 4, q = i & 15;
        float4 v = W4[i];
        unsigned* p = &ws[k * 72 + q * 4];
        p[0] = f2tf(v.x); p[1] = f2tf(v.y); p[2] = f2tf(v.z); p[3] = f2tf(v.w);
    }
    #pragma unroll
    for (int i = tid; i < 4096; i += 256) {      // x tile: 128 rows x 32 float4
        int r = i >> 5, q = i & 31;
        int gr = row0 + r;
        float4 v = (gr < NN) ? x4[gr * 32 + q] : make_float4(0, 0, 0, 0);
        unsigned* p = &xs[r * 132 + q * 4];
        p[0] = f2tf(v.x); p[1] = f2tf(v.y); p[2] = f2tf(v.z); p[3] = f2tf(v.w);
    }
    __syncthreads();

    int warp = tid >> 5, lane = tid & 31;
    int gid = lane >> 2, tig = lane & 3;
    int wr = warp * 16;
    float acc[8][4];
    #pragma unroll
    for (int nt = 0; nt < 8; nt++)
        #pragma unroll
        for (int j = 0; j < 4; j++) acc[nt][j] = 0.f;

    #pragma unroll 4
    for (int ks = 0; ks < 16; ks++) {
        int k0 = ks * 8;
        unsigned a[4];
        a[0] = xs[(wr + gid) * 132 + k0 + tig];
        a[1] = xs[(wr + gid + 8) * 132 + k0 + tig];
        a[2] = xs[(wr + gid) * 132 + k0 + tig + 4];
        a[3] = xs[(wr + gid + 8) * 132 + k0 + tig + 4];
        #pragma unroll
        for (int nt = 0; nt < 8; nt++) {
            unsigned b0 = ws[(k0 + tig) * 72 + nt * 8 + gid];
            unsigned b1 = ws[(k0 + tig + 4) * 72 + nt * 8 + gid];
            mma_tf32(acc[nt], a, b0, b1);
        }
    }

    int r0 = row0 + wr + gid;
    int r1 = r0 + 8;
    float s0 = (r0 < NN) ? g_dinv[r0] : 0.f;
    float s1 = (r1 < NN) ? g_dinv[r1] : 0.f;
    float2* t2 = (float2*)g_t;
    #pragma unroll
    for (int nt = 0; nt < 8; nt++) {
        int c2i = nt * 4 + tig;
        if (r0 < NN) t2[r0 * 32 + c2i] = make_float2(s0 * acc[nt][0], s0 * acc[nt][1]);
        if (r1 < NN) t2[r1 * 32 + c2i] = make_float2(s1 * acc[nt][2], s1 * acc[nt][3]);
    }
}

// CSR gather-reduce, no atomics. LAYER 1: reads g_t (tt), writes g_a = hh =
// dinv*relu(dinv*acc + b1)  (relu fused). LAYER 2: reads g_a, writes g_t =
// dinv*acc (gemm2 input pre-scaled).
template <int LAYER>
__global__ __launch_bounds__(256) void k_aggcsr(const float* __restrict__ b1) {
    int idx = blockIdx.x * 256 + threadIdx.x;
    int d = idx >> 4;
    if (d >= NN) return;
    int sub = idx & 15;
    const float4* t4 = (const float4*)(LAYER == 1 ? g_t : g_a);
    int beg = g_off[d], end = g_off[d + 1];
    float4 acc0 = t4[d * 16 + sub];   // self-loop term
    float4 acc1 = {0, 0, 0, 0};
    int j = beg;
    for (; j + 1 < end; j += 2) {
        int s0 = g_srcs[j];
        int s1 = g_srcs[j + 1];
        float4 v0 = t4[s0 * 16 + sub];
        float4 v1 = t4[s1 * 16 + sub];
        acc0.x += v0.x; acc0.y += v0.y; acc0.z += v0.z; acc0.w += v0.w;
        acc1.x += v1.x; acc1.y += v1.y; acc1.z += v1.z; acc1.w += v1.w;
    }
    if (j < end) {
        int s0 = g_srcs[j];
        float4 v0 = t4[s0 * 16 + sub];
        acc0.x += v0.x; acc0.y += v0.y; acc0.z += v0.z; acc0.w += v0.w;
    }
    acc0.x += acc1.x; acc0.y += acc1.y; acc0.z += acc1.z; acc0.w += acc1.w;
    float s = g_dinv[d];
    if (LAYER == 1) {
        float4 b = ((const float4*)b1)[sub];
        acc0.x = fmaxf(s * acc0.x + b.x, 0.f) * s;
        acc0.y = fmaxf(s * acc0.y + b.y, 0.f) * s;
        acc0.z = fmaxf(s * acc0.z + b.z, 0.f) * s;
        acc0.w = fmaxf(s * acc0.w + b.w, 0.f) * s;
        ((float4*)g_a)[d * 16 + sub] = acc0;
    } else {
        acc0.x *= s; acc0.y *= s; acc0.z *= s; acc0.w *= s;
        ((float4*)g_t)[d * 16 + sub] = acc0;
    }
}

// out = g_t[N,64] @ W2[64,128] + b2 via tf32 mma (input already dinv-scaled).
__global__ __launch_bounds__(256) void k_gemm2(const float* __restrict__ W2,
                                               const float* __restrict__ b2,
                                               float* __restrict__ out) {
    __shared__ unsigned xs[128 * 68];    // tile, tf32, [row][k] pad 68
    __shared__ unsigned ws[64 * 136];    // W2, tf32, [k][n] pad 136
    int tid = threadIdx.x;
    int row0 = blockIdx.x * 128;
    const float4* a4 = (const float4*)g_t;
    const float4* W4 = (const float4*)W2;

    #pragma unroll
    for (int i = tid; i < 2048; i += 256) {      // W2: 64x128 = 2048 float4
        int k = i >> 5, q = i & 31;
        float4 v = W4[i];
        unsigned* p = &ws[k * 136 + q * 4];
        p[0] = f2tf(v.x); p[1] = f2tf(v.y); p[2] = f2tf(v.z); p[3] = f2tf(v.w);
    }
    #pragma unroll
    for (int i = tid; i < 2048; i += 256) {      // tile: 128 rows x 16 float4
        int r = i >> 4, q = i & 15;
        int gr = row0 + r;
        float4 v = (gr < NN) ? a4[gr * 16 + q] : make_float4(0, 0, 0, 0);
        unsigned* p = &xs[r * 68 + q * 4];
        p[0] = f2tf(v.x); p[1] = f2tf(v.y); p[2] = f2tf(v.z); p[3] = f2tf(v.w);
    }
    __syncthreads();

    int warp = tid >> 5, lane = tid & 31;
    int gid = lane >> 2, tig = lane & 3;
    int wr = warp * 16;
    float acc[16][4];
    #pragma unroll
    for (int nt = 0; nt < 16; nt++)
        #pragma unroll
        for (int j = 0; j < 4; j++) acc[nt][j] = 0.f;

    #pragma unroll 2
    for (int ks = 0; ks < 8; ks++) {
        int k0 = ks * 8;
        unsigned a[4];
        a[0] = xs[(wr + gid) * 68 + k0 + tig];
        a[1] = xs[(wr + gid + 8) * 68 + k0 + tig];
        a[2] = xs[(wr + gid) * 68 + k0 + tig + 4];
        a[3] = xs[(wr + gid + 8) * 68 + k0 + tig + 4];
        #pragma unroll
        for (int nt = 0; nt < 16; nt++) {
            unsigned b0 = ws[(k0 + tig) * 136 + nt * 8 + gid];
            unsigned b1 = ws[(k0 + tig + 4) * 136 + nt * 8 + gid];
            mma_tf32(acc[nt], a, b0, b1);
        }
    }

    int r0 = row0 + wr + gid;
    int r1 = r0 + 8;
    float2* o2 = (float2*)out;
    #pragma unroll
    for (int nt = 0; nt < 16; nt++) {
        int col = nt * 8 + 2 * tig;
        float bx = __ldg(&b2[col]), by = __ldg(&b2[col + 1]);
        int c2i = col >> 1;
        if (r0 < NN) o2[r0 * 64 + c2i] = make_float2(acc[nt][0] + bx, acc[nt][1] + by);
        if (r1 < NN) o2[r1 * 64 + c2i] = make_float2(acc[nt][2] + bx, acc[nt][3] + by);
    }
}

extern "C" void kernel_launch(void* const* d_in, const int* in_sizes, int n_in,
                              void* d_out, int out_size) {
    const float* x  = (const float*)d_in[0];
    const int*   ei = (const int*)d_in[1];   // [2, E] int32
    const float* W1 = (const float*)d_in[2];
    const float* b1 = (const float*)d_in[3];
    const float* W2 = (const float*)d_in[4];
    const float* b2 = (const float*)d_in[5];
    float* out = (float*)d_out;

    const int* src = ei;
    const int* dst = ei + NE;

    // CSR build
    k_zero      <<<(NN + 255) / 256, 256>>>();
    k_count     <<<(NE + 255) / 256, 256>>>(dst);
    k_scan1     <<<NB_SCAN, 256>>>();
    k_scan2     <<<1, 128>>>();
    k_scan3     <<<(NN + 255) / 256, 256>>>();
    k_fillcsr   <<<(NE + 255) / 256, 256>>>(src, dst);
    // GCN layers
    k_gemm1     <<<(NN + 127) / 128, 256>>>(x, W1);
    k_aggcsr<1> <<<(NN * 16 + 255) / 256, 256>>>(b1);   // agg + relu fused
    k_aggcsr<2> <<<(NN * 16 + 255) / 256, 256>>>(b1);   // agg + dinv fused
    k_gemm2     <<<(NN + 127) / 128, 256>>>(W2, b2, out);
}

// round 9
// speedup vs baseline: 1.0095x; 1.0095x over previous
#include <cuda_runtime.h>

#define NN 100000
#define NE 1600000
#define NB_SCAN ((NN + 1023) / 1024)   // 98

__device__ int   g_cnt[NN];
__device__ int   g_off[NN + 1];
__device__ int   g_bsum[NB_SCAN];
__device__ int   g_fill[NN];
__device__ int   g_srcs[NE];
__device__ float g_dinv[NN];
__device__ __align__(16) float g_t[NN * 64];   // raw t = x@W1; later dinv*agg2 (gemm2 input)
__device__ __align__(16) float g_a[NN * 64];   // hh = dinv*relu(dinv*agg1 + b1)

__device__ __forceinline__ unsigned f2tf(float f) {
    unsigned u;
    asm("cvt.rna.tf32.f32 %0, %1;" : "=r"(u) : "f"(f));
    return u;
}

__device__ __forceinline__ void mma_tf32(float* d, const unsigned* a, unsigned b0, unsigned b1) {
    asm("mma.sync.aligned.m16n8k8.row.col.f32.tf32.tf32.f32 "
        "{%0,%1,%2,%3},{%4,%5,%6,%7},{%8,%9},{%0,%1,%2,%3};"
        : "+f"(d[0]), "+f"(d[1]), "+f"(d[2]), "+f"(d[3])
        : "r"(a[0]), "r"(a[1]), "r"(a[2]), "r"(a[3]), "r"(b0), "r"(b1));
}

__global__ void k_zero() {
    int i = blockIdx.x * 256 + threadIdx.x;
    if (i < NN) g_cnt[i] = 0;
}

__global__ void k_count(const int* __restrict__ dst) {
    int e = blockIdx.x * 256 + threadIdx.x;
    if (e < NE) atomicAdd(&g_cnt[dst[e]], 1);
}

// Block-local exclusive scan; block totals to g_bsum.
__global__ __launch_bounds__(256) void k_scan1() {
    __shared__ int sh[256];
    int b = blockIdx.x, t = threadIdx.x;
    int base = b * 1024 + t * 4;
    int c0 = (base + 0 < NN) ? g_cnt[base + 0] : 0;
    int c1 = (base + 1 < NN) ? g_cnt[base + 1] : 0;
    int c2 = (base + 2 < NN) ? g_cnt[base + 2] : 0;
    int c3 = (base + 3 < NN) ? g_cnt[base + 3] : 0;
    int s = c0 + c1 + c2 + c3;
    sh[t] = s;
    __syncthreads();
    for (int ofs = 1; ofs < 256; ofs <<= 1) {
        int v = (t >= ofs) ? sh[t - ofs] : 0;
        __syncthreads();
        sh[t] += v;
        __syncthreads();
    }
    int excl = sh[t] - s;
    if (base + 0 < NN) g_off[base + 0] = excl;
    if (base + 1 < NN) g_off[base + 1] = excl + c0;
    if (base + 2 < NN) g_off[base + 2] = excl + c0 + c1;
    if (base + 3 < NN) g_off[base + 3] = excl + c0 + c1 + c2;
    if (t == 255) g_bsum[b] = sh[255];
}

// Finalize offsets (each block re-scans the 98 bsums itself — no scan2 kernel),
// init fill cursors, compute dinv.
__global__ __launch_bounds__(256) void k_scan3() {
    __shared__ int sh[128];
    __shared__ int ex[128];
    int t = threadIdx.x;
    if (t < 128) sh[t] = (t < NB_SCAN) ? g_bsum[t] : 0;
    __syncthreads();
    int orig = (t < 128) ? sh[t] : 0;
    #pragma unroll
    for (int ofs = 1; ofs < 128; ofs <<= 1) {
        int u = (t < 128 && t >= ofs) ? sh[t - ofs] : 0;
        __syncthreads();
        if (t < 128) sh[t] += u;
        __syncthreads();
    }
    if (t < 128) ex[t] = sh[t] - orig;   // exclusive prefix of bucket sums
    __syncthreads();

    int i = blockIdx.x * 256 + t;
    if (i < NN) {
        int o = g_off[i] + ex[i >> 10];
        g_off[i] = o;
        g_fill[i] = o;
        g_dinv[i] = rsqrtf((float)(g_cnt[i] + 1));
    }
    if (blockIdx.x == 0 && t == 0) g_off[NN] = NE;
}

__global__ void k_fillcsr(const int* __restrict__ src, const int* __restrict__ dst) {
    int e = blockIdx.x * 256 + threadIdx.x;
    if (e < NE) {
        int pos = atomicAdd(&g_fill[dst[e]], 1);
        g_srcs[pos] = src[e];
    }
}

// RAW t = x[N,128] @ W1[128,64] via tf32 mma (no dinv — runs concurrent with CSR build).
__global__ __launch_bounds__(256) void k_gemm1(const float* __restrict__ x,
                                               const float* __restrict__ W) {
    __shared__ unsigned xs[128 * 132];
    __shared__ unsigned ws[128 * 72];
    int tid = threadIdx.x;
    int row0 = blockIdx.x * 128;
    const float4* x4 = (const float4*)x;
    const float4* W4 = (const float4*)W;

    #pragma unroll
    for (int i = tid; i < 2048; i += 256) {
        int k = i >> 4, q = i & 15;
        float4 v = W4[i];
        unsigned* p = &ws[k * 72 + q * 4];
        p[0] = f2tf(v.x); p[1] = f2tf(v.y); p[2] = f2tf(v.z); p[3] = f2tf(v.w);
    }
    #pragma unroll
    for (int i = tid; i < 4096; i += 256) {
        int r = i >> 5, q = i & 31;
        int gr = row0 + r;
        float4 v = (gr < NN) ? x4[gr * 32 + q] : make_float4(0, 0, 0, 0);
        unsigned* p = &xs[r * 132 + q * 4];
        p[0] = f2tf(v.x); p[1] = f2tf(v.y); p[2] = f2tf(v.z); p[3] = f2tf(v.w);
    }
    __syncthreads();

    int warp = tid >> 5, lane = tid & 31;
    int gid = lane >> 2, tig = lane & 3;
    int wr = warp * 16;
    float acc[8][4];
    #pragma unroll
    for (int nt = 0; nt < 8; nt++)
        #pragma unroll
        for (int j = 0; j < 4; j++) acc[nt][j] = 0.f;

    #pragma unroll 4
    for (int ks = 0; ks < 16; ks++) {
        int k0 = ks * 8;
        unsigned a[4];
        a[0] = xs[(wr + gid) * 132 + k0 + tig];
        a[1] = xs[(wr + gid + 8) * 132 + k0 + tig];
        a[2] = xs[(wr + gid) * 132 + k0 + tig + 4];
        a[3] = xs[(wr + gid + 8) * 132 + k0 + tig + 4];
        #pragma unroll
        for (int nt = 0; nt < 8; nt++) {
            unsigned b0 = ws[(k0 + tig) * 72 + nt * 8 + gid];
            unsigned b1 = ws[(k0 + tig + 4) * 72 + nt * 8 + gid];
            mma_tf32(acc[nt], a, b0, b1);
        }
    }

    int r0 = row0 + wr + gid;
    int r1 = r0 + 8;
    float2* t2 = (float2*)g_t;
    #pragma unroll
    for (int nt = 0; nt < 8; nt++) {
        int c2i = nt * 4 + tig;
        if (r0 < NN) t2[r0 * 32 + c2i] = make_float2(acc[nt][0], acc[nt][1]);
        if (r1 < NN) t2[r1 * 32 + c2i] = make_float2(acc[nt][2], acc[nt][3]);
    }
}

// CSR gather-reduce, no atomics.
// LAYER 1: reads RAW g_t, weights each row by dinv[s]; out g_a = dinv*relu(dinv*acc + b1).
// LAYER 2: reads pre-scaled g_a; out g_t = dinv*acc.
template <int LAYER>
__global__ __launch_bounds__(256) void k_aggcsr(const float* __restrict__ b1) {
    int idx = blockIdx.x * 256 + threadIdx.x;
    int d = idx >> 4;
    if (d >= NN) return;
    int sub = idx & 15;
    const float4* t4 = (const float4*)(LAYER == 1 ? g_t : g_a);
    int beg = g_off[d], end = g_off[d + 1];
    float s = g_dinv[d];
    float4 acc0, acc1 = {0, 0, 0, 0};
    {
        float4 v = t4[d * 16 + sub];                 // self-loop term
        float w = (LAYER == 1) ? s : 1.f;
        acc0 = make_float4(w * v.x, w * v.y, w * v.z, w * v.w);
    }
    int j = beg;
    for (; j + 1 < end; j += 2) {
        int s0 = g_srcs[j];
        int s1 = g_srcs[j + 1];
        float4 v0 = t4[s0 * 16 + sub];
        float4 v1 = t4[s1 * 16 + sub];
        if (LAYER == 1) {
            float n0 = g_dinv[s0], n1 = g_dinv[s1];
            acc0.x += n0 * v0.x; acc0.y += n0 * v0.y; acc0.z += n0 * v0.z; acc0.w += n0 * v0.w;
            acc1.x += n1 * v1.x; acc1.y += n1 * v1.y; acc1.z += n1 * v1.z; acc1.w += n1 * v1.w;
        } else {
            acc0.x += v0.x; acc0.y += v0.y; acc0.z += v0.z; acc0.w += v0.w;
            acc1.x += v1.x; acc1.y += v1.y; acc1.z += v1.z; acc1.w += v1.w;
        }
    }
    if (j < end) {
        int s0 = g_srcs[j];
        float4 v0 = t4[s0 * 16 + sub];
        float n0 = (LAYER == 1) ? g_dinv[s0] : 1.f;
        acc0.x += n0 * v0.x; acc0.y += n0 * v0.y; acc0.z += n0 * v0.z; acc0.w += n0 * v0.w;
    }
    acc0.x += acc1.x; acc0.y += acc1.y; acc0.z += acc1.z; acc0.w += acc1.w;
    if (LAYER == 1) {
        float4 b = ((const float4*)b1)[sub];
        acc0.x = fmaxf(s * acc0.x + b.x, 0.f) * s;
        acc0.y = fmaxf(s * acc0.y + b.y, 0.f) * s;
        acc0.z = fmaxf(s * acc0.z + b.z, 0.f) * s;
        acc0.w = fmaxf(s * acc0.w + b.w, 0.f) * s;
        ((float4*)g_a)[d * 16 + sub] = acc0;
    } else {
        acc0.x *= s; acc0.y *= s; acc0.z *= s; acc0.w *= s;
        ((float4*)g_t)[d * 16 + sub] = acc0;
    }
}

// out = g_t[N,64] @ W2[64,128] + b2 via tf32 mma (input already dinv-scaled).
__global__ __launch_bounds__(256) void k_gemm2(const float* __restrict__ W2,
                                               const float* __restrict__ b2,
                                               float* __restrict__ out) {
    __shared__ unsigned xs[128 * 68];
    __shared__ unsigned ws[64 * 136];
    int tid = threadIdx.x;
    int row0 = blockIdx.x * 128;
    const float4* a4 = (const float4*)g_t;
    const float4* W4 = (const float4*)W2;

    #pragma unroll
    for (int i = tid; i < 2048; i += 256) {
        int k = i >> 5, q = i & 31;
        float4 v = W4[i];
        unsigned* p = &ws[k * 136 + q * 4];
        p[0] = f2tf(v.x); p[1] = f2tf(v.y); p[2] = f2tf(v.z); p[3] = f2tf(v.w);
    }
    #pragma unroll
    for (int i = tid; i < 2048; i += 256) {
        int r = i >> 4, q = i & 15;
        int gr = row0 + r;
        float4 v = (gr < NN) ? a4[gr * 16 + q] : make_float4(0, 0, 0, 0);
        unsigned* p = &xs[r * 68 + q * 4];
        p[0] = f2tf(v.x); p[1] = f2tf(v.y); p[2] = f2tf(v.z); p[3] = f2tf(v.w);
    }
    __syncthreads();

    int warp = tid >> 5, lane = tid & 31;
    int gid = lane >> 2, tig = lane & 3;
    int wr = warp * 16;
    float acc[16][4];
    #pragma unroll
    for (int nt = 0; nt < 16; nt++)
        #pragma unroll
        for (int j = 0; j < 4; j++) acc[nt][j] = 0.f;

    #pragma unroll 2
    for (int ks = 0; ks < 8; ks++) {
        int k0 = ks * 8;
        unsigned a[4];
        a[0] = xs[(wr + gid) * 68 + k0 + tig];
        a[1] = xs[(wr + gid + 8) * 68 + k0 + tig];
        a[2] = xs[(wr + gid) * 68 + k0 + tig + 4];
        a[3] = xs[(wr + gid + 8) * 68 + k0 + tig + 4];
        #pragma unroll
        for (int nt = 0; nt < 16; nt++) {
            unsigned b0 = ws[(k0 + tig) * 136 + nt * 8 + gid];
            unsigned b1 = ws[(k0 + tig + 4) * 136 + nt * 8 + gid];
            mma_tf32(acc[nt], a, b0, b1);
        }
    }

    int r0 = row0 + wr + gid;
    int r1 = r0 + 8;
    float2* o2 = (float2*)out;
    #pragma unroll
    for (int nt = 0; nt < 16; nt++) {
        int col = nt * 8 + 2 * tig;
        float bx = __ldg(&b2[col]), by = __ldg(&b2[col + 1]);
        int c2i = col >> 1;
        if (r0 < NN) o2[r0 * 64 + c2i] = make_float2(acc[nt][0] + bx, acc[nt][1] + by);
        if (r1 < NN) o2[r1 * 64 + c2i] = make_float2(acc[nt][2] + bx, acc[nt][3] + by);
    }
}

extern "C" void kernel_launch(void* const* d_in, const int* in_sizes, int n_in,
                              void* d_out, int out_size) {
    const float* x  = (const float*)d_in[0];
    const int*   ei = (const int*)d_in[1];   // [2, E] int32
    const float* W1 = (const float*)d_in[2];
    const float* b1 = (const float*)d_in[3];
    const float* W2 = (const float*)d_in[4];
    const float* b2 = (const float*)d_in[5];
    float* out = (float*)d_out;

    const int* src = ei;
    const int* dst = ei + NE;

    // Side stream + events for the capture-legal fork (created once; host-side
    // objects only, no device memory).
    static cudaStream_t s2 = nullptr;
    static cudaEvent_t e_fork = nullptr, e_join = nullptr;
    if (!s2) {
        cudaStreamCreateWithFlags(&s2, cudaStreamNonBlocking);
        cudaEventCreateWithFlags(&e_fork, cudaEventDisableTiming);
        cudaEventCreateWithFlags(&e_join, cudaEventDisableTiming);
    }

    // Fork: gemm1 (independent of graph structure) runs parallel to CSR build.
    cudaEventRecord(e_fork, 0);
    cudaStreamWaitEvent(s2, e_fork, 0);
    k_gemm1<<<(NN + 127) / 128, 256, 0, s2>>>(x, W1);
    cudaEventRecord(e_join, s2);

    // CSR build on the main (capture) stream.
    k_zero   <<<(NN + 255) / 256, 256>>>();
    k_count  <<<(NE + 255) / 256, 256>>>(dst);
    k_scan1  <<<NB_SCAN, 256>>>();
    k_scan3  <<<(NN + 255) / 256, 256>>>();
    k_fillcsr<<<(NE + 255) / 256, 256>>>(src, dst);

    // Join, then the dependent chain.
    cudaStreamWaitEvent(0, e_join, 0);
    k_aggcsr<1><<<(NN * 16 + 255) / 256, 256>>>(b1);   // agg + dinv-weight + relu
    k_aggcsr<2><<<(NN * 16 + 255) / 256, 256>>>(b1);   // agg + dinv
    k_gemm2    <<<(NN + 127) / 128, 256>>>(W2, b2, out);
}

// round 10
// speedup vs baseline: 1.0937x; 1.0834x over previous
#include <cuda_runtime.h>
#include <cuda_fp16.h>

#define NN 100000
#define NE 1600000
#define NB_SCAN ((NN + 1023) / 1024)   // 98

__device__ int   g_cnt[NN];
__device__ int   g_off[NN + 1];
__device__ int   g_bsum[NB_SCAN];
__device__ int   g_fill[NN];
__device__ int   g_srcs[NE];
__device__ float g_dinv[NN];
// Gather tables in fp16 (same 10-bit mantissa as tf32): 12.8 MB each.
__device__ __align__(16) __half g_t[NN * 64];   // raw t = x@W1; later dinv*agg2 (gemm2 input)
__device__ __align__(16) __half g_a[NN * 64];   // hh = dinv*relu(dinv*agg1 + b1)

__device__ __forceinline__ unsigned f2tf(float f) {
    unsigned u;
    asm("cvt.rna.tf32.f32 %0, %1;" : "=r"(u) : "f"(f));
    return u;
}

__device__ __forceinline__ void mma_tf32(float* d, const unsigned* a, unsigned b0, unsigned b1) {
    asm("mma.sync.aligned.m16n8k8.row.col.f32.tf32.tf32.f32 "
        "{%0,%1,%2,%3},{%4,%5,%6,%7},{%8,%9},{%0,%1,%2,%3};"
        : "+f"(d[0]), "+f"(d[1]), "+f"(d[2]), "+f"(d[3])
        : "r"(a[0]), "r"(a[1]), "r"(a[2]), "r"(a[3]), "r"(b0), "r"(b1));
}

__global__ void k_zero() {
    int i = blockIdx.x * 256 + threadIdx.x;
    if (i < NN) g_cnt[i] = 0;
}

__global__ void k_count(const int* __restrict__ dst) {
    int e = blockIdx.x * 256 + threadIdx.x;
    if (e < NE) atomicAdd(&g_cnt[dst[e]], 1);
}

// Block-local exclusive scan; block totals to g_bsum.
__global__ __launch_bounds__(256) void k_scan1() {
    __shared__ int sh[256];
    int b = blockIdx.x, t = threadIdx.x;
    int base = b * 1024 + t * 4;
    int c0 = (base + 0 < NN) ? g_cnt[base + 0] : 0;
    int c1 = (base + 1 < NN) ? g_cnt[base + 1] : 0;
    int c2 = (base + 2 < NN) ? g_cnt[base + 2] : 0;
    int c3 = (base + 3 < NN) ? g_cnt[base + 3] : 0;
    int s = c0 + c1 + c2 + c3;
    sh[t] = s;
    __syncthreads();
    for (int ofs = 1; ofs < 256; ofs <<= 1) {
        int v = (t >= ofs) ? sh[t - ofs] : 0;
        __syncthreads();
        sh[t] += v;
        __syncthreads();
    }
    int excl = sh[t] - s;
    if (base + 0 < NN) g_off[base + 0] = excl;
    if (base + 1 < NN) g_off[base + 1] = excl + c0;
    if (base + 2 < NN) g_off[base + 2] = excl + c0 + c1;
    if (base + 3 < NN) g_off[base + 3] = excl + c0 + c1 + c2;
    if (t == 255) g_bsum[b] = sh[255];
}

// Finalize offsets (each block re-scans the 98 bsums itself), init fill
// cursors, compute dinv.
__global__ __launch_bounds__(256) void k_scan3() {
    __shared__ int sh[128];
    __shared__ int ex[128];
    int t = threadIdx.x;
    if (t < 128) sh[t] = (t < NB_SCAN) ? g_bsum[t] : 0;
    __syncthreads();
    int orig = (t < 128) ? sh[t] : 0;
    #pragma unroll
    for (int ofs = 1; ofs < 128; ofs <<= 1) {
        int u = (t < 128 && t >= ofs) ? sh[t - ofs] : 0;
        __syncthreads();
        if (t < 128) sh[t] += u;
        __syncthreads();
    }
    if (t < 128) ex[t] = sh[t] - orig;
    __syncthreads();

    int i = blockIdx.x * 256 + t;
    if (i < NN) {
        int o = g_off[i] + ex[i >> 10];
        g_off[i] = o;
        g_fill[i] = o;
        g_dinv[i] = rsqrtf((float)(g_cnt[i] + 1));
    }
    if (blockIdx.x == 0 && t == 0) g_off[NN] = NE;
}

__global__ void k_fillcsr(const int* __restrict__ src, const int* __restrict__ dst) {
    int e = blockIdx.x * 256 + threadIdx.x;
    if (e < NE) {
        int pos = atomicAdd(&g_fill[dst[e]], 1);
        g_srcs[pos] = src[e];
    }
}

// RAW t = x[N,128] @ W1[128,64] via tf32 mma; result stored fp16.
__global__ __launch_bounds__(256) void k_gemm1(const float* __restrict__ x,
                                               const float* __restrict__ W) {
    __shared__ unsigned xs[128 * 132];
    __shared__ unsigned ws[128 * 72];
    int tid = threadIdx.x;
    int row0 = blockIdx.x * 128;
    const float4* x4 = (const float4*)x;
    const float4* W4 = (const float4*)W;

    #pragma unroll
    for (int i = tid; i < 2048; i += 256) {
        int k = i >> 4, q = i & 15;
        float4 v = W4[i];
        unsigned* p = &ws[k * 72 + q * 4];
        p[0] = f2tf(v.x); p[1] = f2tf(v.y); p[2] = f2tf(v.z); p[3] = f2tf(v.w);
    }
    #pragma unroll
    for (int i = tid; i < 4096; i += 256) {
        int r = i >> 5, q = i & 31;
        int gr = row0 + r;
        float4 v = (gr < NN) ? x4[gr * 32 + q] : make_float4(0, 0, 0, 0);
        unsigned* p = &xs[r * 132 + q * 4];
        p[0] = f2tf(v.x); p[1] = f2tf(v.y); p[2] = f2tf(v.z); p[3] = f2tf(v.w);
    }
    __syncthreads();

    int warp = tid >> 5, lane = tid & 31;
    int gid = lane >> 2, tig = lane & 3;
    int wr = warp * 16;
    float acc[8][4];
    #pragma unroll
    for (int nt = 0; nt < 8; nt++)
        #pragma unroll
        for (int j = 0; j < 4; j++) acc[nt][j] = 0.f;

    #pragma unroll 4
    for (int ks = 0; ks < 16; ks++) {
        int k0 = ks * 8;
        unsigned a[4];
        a[0] = xs[(wr + gid) * 132 + k0 + tig];
        a[1] = xs[(wr + gid + 8) * 132 + k0 + tig];
        a[2] = xs[(wr + gid) * 132 + k0 + tig + 4];
        a[3] = xs[(wr + gid + 8) * 132 + k0 + tig + 4];
        #pragma unroll
        for (int nt = 0; nt < 8; nt++) {
            unsigned b0 = ws[(k0 + tig) * 72 + nt * 8 + gid];
            unsigned b1 = ws[(k0 + tig + 4) * 72 + nt * 8 + gid];
            mma_tf32(acc[nt], a, b0, b1);
        }
    }

    int r0 = row0 + wr + gid;
    int r1 = r0 + 8;
    __half2* t2 = (__half2*)g_t;   // row = 32 half2
    #pragma unroll
    for (int nt = 0; nt < 8; nt++) {
        int c2i = nt * 4 + tig;     // half2 index of cols (nt*8+2tig, +1)
        if (r0 < NN) t2[r0 * 32 + c2i] = __floats2half2_rn(acc[nt][0], acc[nt][1]);
        if (r1 < NN) t2[r1 * 32 + c2i] = __floats2half2_rn(acc[nt][2], acc[nt][3]);
    }
}

// CSR gather-reduce over fp16 rows (128B/row), fp32 accumulate, no atomics.
// LAYER 1: reads raw g_t, weights rows by dinv[s]; writes g_a = dinv*relu(dinv*acc+b1) (fp16).
// LAYER 2: reads pre-scaled g_a; writes g_t = dinv*acc (fp16).
template <int LAYER>
__global__ __launch_bounds__(256) void k_aggcsr(const float* __restrict__ b1) {
    int idx = blockIdx.x * 256 + threadIdx.x;
    int d = idx >> 4;
    if (d >= NN) return;
    int sub = idx & 15;                       // 16 threads/node, 8B (4 halves) each
    const uint2* t8 = (const uint2*)(LAYER == 1 ? g_t : g_a);   // row = 16 uint2
    int beg = g_off[d], end = g_off[d + 1];
    float s = g_dinv[d];

    float4 acc0, acc1 = {0, 0, 0, 0};
    {
        uint2 u = t8[d * 16 + sub];           // self-loop term
        float2 f0 = __half22float2(*(const __half2*)&u.x);
        float2 f1 = __half22float2(*(const __half2*)&u.y);
        float w = (LAYER == 1) ? s : 1.f;
        acc0 = make_float4(w * f0.x, w * f0.y, w * f1.x, w * f1.y);
    }
    int j = beg;
    for (; j + 1 < end; j += 2) {
        int s0 = g_srcs[j];
        int s1 = g_srcs[j + 1];
        uint2 u0 = t8[s0 * 16 + sub];
        uint2 u1 = t8[s1 * 16 + sub];
        float2 a0 = __half22float2(*(const __half2*)&u0.x);
        float2 a1 = __half22float2(*(const __half2*)&u0.y);
        float2 b0 = __half22float2(*(const __half2*)&u1.x);
        float2 b1f = __half22float2(*(const __half2*)&u1.y);
        if (LAYER == 1) {
            float n0 = g_dinv[s0], n1 = g_dinv[s1];
            acc0.x += n0 * a0.x; acc0.y += n0 * a0.y; acc0.z += n0 * a1.x; acc0.w += n0 * a1.y;
            acc1.x += n1 * b0.x; acc1.y += n1 * b0.y; acc1.z += n1 * b1f.x; acc1.w += n1 * b1f.y;
        } else {
            acc0.x += a0.x; acc0.y += a0.y; acc0.z += a1.x; acc0.w += a1.y;
            acc1.x += b0.x; acc1.y += b0.y; acc1.z += b1f.x; acc1.w += b1f.y;
        }
    }
    if (j < end) {
        int s0 = g_srcs[j];
        uint2 u0 = t8[s0 * 16 + sub];
        float2 a0 = __half22float2(*(const __half2*)&u0.x);
        float2 a1 = __half22float2(*(const __half2*)&u0.y);
        float n0 = (LAYER == 1) ? g_dinv[s0] : 1.f;
        acc0.x += n0 * a0.x; acc0.y += n0 * a0.y; acc0.z += n0 * a1.x; acc0.w += n0 * a1.y;
    }
    acc0.x += acc1.x; acc0.y += acc1.y; acc0.z += acc1.z; acc0.w += acc1.w;

    if (LAYER == 1) {
        float4 b = ((const float4*)b1)[sub];
        acc0.x = fmaxf(s * acc0.x + b.x, 0.f) * s;
        acc0.y = fmaxf(s * acc0.y + b.y, 0.f) * s;
        acc0.z = fmaxf(s * acc0.z + b.z, 0.f) * s;
        acc0.w = fmaxf(s * acc0.w + b.w, 0.f) * s;
        uint2 o;
        *(__half2*)&o.x = __floats2half2_rn(acc0.x, acc0.y);
        *(__half2*)&o.y = __floats2half2_rn(acc0.z, acc0.w);
        ((uint2*)g_a)[d * 16 + sub] = o;
    } else {
        uint2 o;
        *(__half2*)&o.x = __floats2half2_rn(s * acc0.x, s * acc0.y);
        *(__half2*)&o.y = __floats2half2_rn(s * acc0.z, s * acc0.w);
        ((uint2*)g_t)[d * 16 + sub] = o;
    }
}

// out = g_t[N,64](fp16, already dinv-scaled) @ W2[64,128] + b2 via tf32 mma.
__global__ __launch_bounds__(256) void k_gemm2(const float* __restrict__ W2,
                                               const float* __restrict__ b2,
                                               float* __restrict__ out) {
    __shared__ unsigned xs[128 * 68];
    __shared__ unsigned ws[64 * 136];
    int tid = threadIdx.x;
    int row0 = blockIdx.x * 128;
    const uint2* a8 = (const uint2*)g_t;     // row = 16 uint2 (4 halves each)
    const float4* W4 = (const float4*)W2;

    #pragma unroll
    for (int i = tid; i < 2048; i += 256) {
        int k = i >> 5, q = i & 31;
        float4 v = W4[i];
        unsigned* p = &ws[k * 136 + q * 4];
        p[0] = f2tf(v.x); p[1] = f2tf(v.y); p[2] = f2tf(v.z); p[3] = f2tf(v.w);
    }
    #pragma unroll
    for (int i = tid; i < 2048; i += 256) {
        int r = i >> 4, q = i & 15;
        int gr = row0 + r;
        float2 f0 = {0, 0}, f1 = {0, 0};
        if (gr < NN) {
            uint2 u = a8[gr * 16 + q];
            f0 = __half22float2(*(const __half2*)&u.x);
            f1 = __half22float2(*(const __half2*)&u.y);
        }
        unsigned* p = &xs[r * 68 + q * 4];
        p[0] = f2tf(f0.x); p[1] = f2tf(f0.y); p[2] = f2tf(f1.x); p[3] = f2tf(f1.y);
    }
    __syncthreads();

    int warp = tid >> 5, lane = tid & 31;
    int gid = lane >> 2, tig = lane & 3;
    int wr = warp * 16;
    float acc[16][4];
    #pragma unroll
    for (int nt = 0; nt < 16; nt++)
        #pragma unroll
        for (int j = 0; j < 4; j++) acc[nt][j] = 0.f;

    #pragma unroll 2
    for (int ks = 0; ks < 8; ks++) {
        int k0 = ks * 8;
        unsigned a[4];
        a[0] = xs[(wr + gid) * 68 + k0 + tig];
        a[1] = xs[(wr + gid + 8) * 68 + k0 + tig];
        a[2] = xs[(wr + gid) * 68 + k0 + tig + 4];
        a[3] = xs[(wr + gid + 8) * 68 + k0 + tig + 4];
        #pragma unroll
        for (int nt = 0; nt < 16; nt++) {
            unsigned b0 = ws[(k0 + tig) * 136 + nt * 8 + gid];
            unsigned b1 = ws[(k0 + tig + 4) * 136 + nt * 8 + gid];
            mma_tf32(acc[nt], a, b0, b1);
        }
    }

    int r0 = row0 + wr + gid;
    int r1 = r0 + 8;
    float2* o2 = (float2*)out;
    #pragma unroll
    for (int nt = 0; nt < 16; nt++) {
        int col = nt * 8 + 2 * tig;
        float bx = __ldg(&b2[col]), by = __ldg(&b2[col + 1]);
        int c2i = col >> 1;
        if (r0 < NN) o2[r0 * 64 + c2i] = make_float2(acc[nt][0] + bx, acc[nt][1] + by);
        if (r1 < NN) o2[r1 * 64 + c2i] = make_float2(acc[nt][2] + bx, acc[nt][3] + by);
    }
}

extern "C" void kernel_launch(void* const* d_in, const int* in_sizes, int n_in,
                              void* d_out, int out_size) {
    const float* x  = (const float*)d_in[0];
    const int*   ei = (const int*)d_in[1];   // [2, E] int32
    const float* W1 = (const float*)d_in[2];
    const float* b1 = (const float*)d_in[3];
    const float* W2 = (const float*)d_in[4];
    const float* b2 = (const float*)d_in[5];
    float* out = (float*)d_out;

    const int* src = ei;
    const int* dst = ei + NE;

    static cudaStream_t s2 = nullptr;
    static cudaEvent_t e_fork = nullptr, e_join = nullptr;
    if (!s2) {
        cudaStreamCreateWithFlags(&s2, cudaStreamNonBlocking);
        cudaEventCreateWithFlags(&e_fork, cudaEventDisableTiming);
        cudaEventCreateWithFlags(&e_join, cudaEventDisableTiming);
    }

    // Fork: gemm1 runs parallel to CSR build.
    cudaEventRecord(e_fork, 0);
    cudaStreamWaitEvent(s2, e_fork, 0);
    k_gemm1<<<(NN + 127) / 128, 256, 0, s2>>>(x, W1);
    cudaEventRecord(e_join, s2);

    // CSR build on the main (capture) stream.
    k_zero   <<<(NN + 255) / 256, 256>>>();
    k_count  <<<(NE + 255) / 256, 256>>>(dst);
    k_scan1  <<<NB_SCAN, 256>>>();
    k_scan3  <<<(NN + 255) / 256, 256>>>();
    k_fillcsr<<<(NE + 255) / 256, 256>>>(src, dst);

    cudaStreamWaitEvent(0, e_join, 0);
    k_aggcsr<1><<<(NN * 16 + 255) / 256, 256>>>(b1);
    k_aggcsr<2><<<(NN * 16 + 255) / 256, 256>>>(b1);
    k_gemm2    <<<(NN + 127) / 128, 256>>>(W2, b2, out);
}

// round 12
// speedup vs baseline: 1.1551x; 1.0562x over previous
#include <cuda_runtime.h>
#include <cuda_fp16.h>

#define NN 100000
#define NE 1600000
#define NB_SCAN ((NN + 1023) / 1024)   // 98

__device__ int   g_cnt[NN];
__device__ int   g_off[NN + 1];
__device__ int   g_bsum[NB_SCAN];
__device__ int   g_fill[NN];
__device__ int   g_srcs[NE];
__device__ float g_dinv[NN];
// Gather tables in fp16 (same 10-bit mantissa as tf32): 12.8 MB each.
__device__ __align__(16) __half g_t[NN * 64];   // raw t = x@W1; later dinv*agg2 (gemm2 input)
__device__ __align__(16) __half g_a[NN * 64];   // hh = dinv*relu(dinv*agg1 + b1)

__device__ __forceinline__ unsigned f2tf(float f) {
    unsigned u;
    asm("cvt.rna.tf32.f32 %0, %1;" : "=r"(u) : "f"(f));
    return u;
}

__device__ __forceinline__ void mma_tf32(float* d, const unsigned* a, unsigned b0, unsigned b1) {
    asm("mma.sync.aligned.m16n8k8.row.col.f32.tf32.tf32.f32 "
        "{%0,%1,%2,%3},{%4,%5,%6,%7},{%8,%9},{%0,%1,%2,%3};"
        : "+f"(d[0]), "+f"(d[1]), "+f"(d[2]), "+f"(d[3])
        : "r"(a[0]), "r"(a[1]), "r"(a[2]), "r"(a[3]), "r"(b0), "r"(b1));
}

// Accumulate 8 halves (one uint4) into 8 floats with weight w.
__device__ __forceinline__ void acc8(float* acc, uint4 u, float w) {
    float2 f0 = __half22float2(*(const __half2*)&u.x);
    float2 f1 = __half22float2(*(const __half2*)&u.y);
    float2 f2 = __half22float2(*(const __half2*)&u.z);
    float2 f3 = __half22float2(*(const __half2*)&u.w);
    acc[0] += w * f0.x; acc[1] += w * f0.y;
    acc[2] += w * f1.x; acc[3] += w * f1.y;
    acc[4] += w * f2.x; acc[5] += w * f2.y;
    acc[6] += w * f3.x; acc[7] += w * f3.y;
}

__global__ void k_zero() {
    int i = blockIdx.x * 256 + threadIdx.x;
    if (i < NN) g_cnt[i] = 0;
}

__global__ void k_count(const int* __restrict__ dst) {
    int e = blockIdx.x * 256 + threadIdx.x;
    if (e < NE) atomicAdd(&g_cnt[dst[e]], 1);
}

// Block-local exclusive scan; block totals to g_bsum.
__global__ __launch_bounds__(256) void k_scan1() {
    __shared__ int sh[256];
    int b = blockIdx.x, t = threadIdx.x;
    int base = b * 1024 + t * 4;
    int c0 = (base + 0 < NN) ? g_cnt[base + 0] : 0;
    int c1 = (base + 1 < NN) ? g_cnt[base + 1] : 0;
    int c2 = (base + 2 < NN) ? g_cnt[base + 2] : 0;
    int c3 = (base + 3 < NN) ? g_cnt[base + 3] : 0;
    int s = c0 + c1 + c2 + c3;
    sh[t] = s;
    __syncthreads();
    for (int ofs = 1; ofs < 256; ofs <<= 1) {
        int v = (t >= ofs) ? sh[t - ofs] : 0;
        __syncthreads();
        sh[t] += v;
        __syncthreads();
    }
    int excl = sh[t] - s;
    if (base + 0 < NN) g_off[base + 0] = excl;
    if (base + 1 < NN) g_off[base + 1] = excl + c0;
    if (base + 2 < NN) g_off[base + 2] = excl + c0 + c1;
    if (base + 3 < NN) g_off[base + 3] = excl + c0 + c1 + c2;
    if (t == 255) g_bsum[b] = sh[255];
}

// Finalize offsets (each block re-scans the 98 bsums itself), init fill
// cursors, compute dinv.
__global__ __launch_bounds__(256) void k_scan3() {
    __shared__ int sh[128];
    __shared__ int ex[128];
    int t = threadIdx.x;
    if (t < 128) sh[t] = (t < NB_SCAN) ? g_bsum[t] : 0;
    __syncthreads();
    int orig = (t < 128) ? sh[t] : 0;
    #pragma unroll
    for (int ofs = 1; ofs < 128; ofs <<= 1) {
        int u = (t < 128 && t >= ofs) ? sh[t - ofs] : 0;
        __syncthreads();
        if (t < 128) sh[t] += u;
        __syncthreads();
    }
    if (t < 128) ex[t] = sh[t] - orig;
    __syncthreads();

    int i = blockIdx.x * 256 + t;
    if (i < NN) {
        int o = g_off[i] + ex[i >> 10];
        g_off[i] = o;
        g_fill[i] = o;
        g_dinv[i] = rsqrtf((float)(g_cnt[i] + 1));
    }
    if (blockIdx.x == 0 && t == 0) g_off[NN] = NE;
}

__global__ void k_fillcsr(const int* __restrict__ src, const int* __restrict__ dst) {
    int e = blockIdx.x * 256 + threadIdx.x;
    if (e < NE) {
        int pos = atomicAdd(&g_fill[dst[e]], 1);
        g_srcs[pos] = src[e];
    }
}

// RAW t = x[N,128] @ W1[128,64] via tf32 mma; result stored fp16.
__global__ __launch_bounds__(256) void k_gemm1(const float* __restrict__ x,
                                               const float* __restrict__ W) {
    __shared__ unsigned xs[128 * 132];
    __shared__ unsigned ws[128 * 72];
    int tid = threadIdx.x;
    int row0 = blockIdx.x * 128;
    const float4* x4 = (const float4*)x;
    const float4* W4 = (const float4*)W;

    #pragma unroll
    for (int i = tid; i < 2048; i += 256) {
        int k = i >> 4, q = i & 15;
        float4 v = W4[i];
        unsigned* p = &ws[k * 72 + q * 4];
        p[0] = f2tf(v.x); p[1] = f2tf(v.y); p[2] = f2tf(v.z); p[3] = f2tf(v.w);
    }
    #pragma unroll
    for (int i = tid; i < 4096; i += 256) {
        int r = i >> 5, q = i & 31;
        int gr = row0 + r;
        float4 v = (gr < NN) ? x4[gr * 32 + q] : make_float4(0, 0, 0, 0);
        unsigned* p = &xs[r * 132 + q * 4];
        p[0] = f2tf(v.x); p[1] = f2tf(v.y); p[2] = f2tf(v.z); p[3] = f2tf(v.w);
    }
    __syncthreads();

    int warp = tid >> 5, lane = tid & 31;
    int gid = lane >> 2, tig = lane & 3;
    int wr = warp * 16;
    float acc[8][4];
    #pragma unroll
    for (int nt = 0; nt < 8; nt++)
        #pragma unroll
        for (int j = 0; j < 4; j++) acc[nt][j] = 0.f;

    #pragma unroll 4
    for (int ks = 0; ks < 16; ks++) {
        int k0 = ks * 8;
        unsigned a[4];
        a[0] = xs[(wr + gid) * 132 + k0 + tig];
        a[1] = xs[(wr + gid + 8) * 132 + k0 + tig];
        a[2] = xs[(wr + gid) * 132 + k0 + tig + 4];
        a[3] = xs[(wr + gid + 8) * 132 + k0 + tig + 4];
        #pragma unroll
        for (int nt = 0; nt < 8; nt++) {
            unsigned b0 = ws[(k0 + tig) * 72 + nt * 8 + gid];
            unsigned b1 = ws[(k0 + tig + 4) * 72 + nt * 8 + gid];
            mma_tf32(acc[nt], a, b0, b1);
        }
    }

    int r0 = row0 + wr + gid;
    int r1 = r0 + 8;
    __half2* t2 = (__half2*)g_t;   // row = 32 half2
    #pragma unroll
    for (int nt = 0; nt < 8; nt++) {
        int c2i = nt * 4 + tig;
        if (r0 < NN) t2[r0 * 32 + c2i] = __floats2half2_rn(acc[nt][0], acc[nt][1]);
        if (r1 < NN) t2[r1 * 32 + c2i] = __floats2half2_rn(acc[nt][2], acc[nt][3]);
    }
}

// CSR gather-reduce over fp16 rows, fp32 accumulate, no atomics.
// 8 threads/node x uint4 (16B = 8 halves) each; 4-way unrolled gather (MLP=4).
// LAYER 1: reads raw g_t, weights rows by dinv[s]; writes g_a = dinv*relu(dinv*acc+b1).
// LAYER 2: reads pre-scaled g_a; writes g_t = dinv*acc.
template <int LAYER>
__global__ __launch_bounds__(256) void k_aggcsr(const float* __restrict__ b1) {
    int idx = blockIdx.x * 256 + threadIdx.x;
    int d = idx >> 3;
    if (d >= NN) return;
    int sub = idx & 7;                        // 8 threads/node
    const uint4* t16 = (const uint4*)(LAYER == 1 ? g_t : g_a);   // row = 8 uint4
    int beg = g_off[d], end = g_off[d + 1];
    float s = g_dinv[d];

    float acc[8];
    #pragma unroll
    for (int i = 0; i < 8; i++) acc[i] = 0.f;
    acc8(acc, t16[d * 8 + sub], (LAYER == 1) ? s : 1.f);   // self-loop term

    int j = beg;
    for (; j + 3 < end; j += 4) {
        int s0 = g_srcs[j + 0];
        int s1 = g_srcs[j + 1];
        int s2 = g_srcs[j + 2];
        int s3 = g_srcs[j + 3];
        uint4 u0 = t16[s0 * 8 + sub];
        uint4 u1 = t16[s1 * 8 + sub];
        uint4 u2 = t16[s2 * 8 + sub];
        uint4 u3 = t16[s3 * 8 + sub];
        if (LAYER == 1) {
            acc8(acc, u0, g_dinv[s0]);
            acc8(acc, u1, g_dinv[s1]);
            acc8(acc, u2, g_dinv[s2]);
            acc8(acc, u3, g_dinv[s3]);
        } else {
            acc8(acc, u0, 1.f);
            acc8(acc, u1, 1.f);
            acc8(acc, u2, 1.f);
            acc8(acc, u3, 1.f);
        }
    }
    for (; j < end; j++) {
        int s0 = g_srcs[j];
        uint4 u0 = t16[s0 * 8 + sub];
        acc8(acc, u0, (LAYER == 1) ? g_dinv[s0] : 1.f);
    }

    uint4 o;
    if (LAYER == 1) {
        const float4* b4 = (const float4*)b1;
        float4 ba = b4[sub * 2], bb = b4[sub * 2 + 1];
        float b[8] = {ba.x, ba.y, ba.z, ba.w, bb.x, bb.y, bb.z, bb.w};
        #pragma unroll
        for (int i = 0; i < 8; i++) acc[i] = fmaxf(s * acc[i] + b[i], 0.f) * s;
        *(__half2*)&o.x = __floats2half2_rn(acc[0], acc[1]);
        *(__half2*)&o.y = __floats2half2_rn(acc[2], acc[3]);
        *(__half2*)&o.z = __floats2half2_rn(acc[4], acc[5]);
        *(__half2*)&o.w = __floats2half2_rn(acc[6], acc[7]);
        ((uint4*)g_a)[d * 8 + sub] = o;
    } else {
        #pragma unroll
        for (int i = 0; i < 8; i++) acc[i] *= s;
        *(__half2*)&o.x = __floats2half2_rn(acc[0], acc[1]);
        *(__half2*)&o.y = __floats2half2_rn(acc[2], acc[3]);
        *(__half2*)&o.z = __floats2half2_rn(acc[4], acc[5]);
        *(__half2*)&o.w = __floats2half2_rn(acc[6], acc[7]);
        ((uint4*)g_t)[d * 8 + sub] = o;
    }
}

// out = g_t[N,64](fp16, already dinv-scaled) @ W2[64,128] + b2 via tf32 mma.
__global__ __launch_bounds__(256) void k_gemm2(const float* __restrict__ W2,
                                               const float* __restrict__ b2,
                                               float* __restrict__ out) {
    __shared__ unsigned xs[128 * 68];
    __shared__ unsigned ws[64 * 136];
    int tid = threadIdx.x;
    int row0 = blockIdx.x * 128;
    const uint2* a8 = (const uint2*)g_t;
    const float4* W4 = (const float4*)W2;

    #pragma unroll
    for (int i = tid; i < 2048; i += 256) {
        int k = i >> 5, q = i & 31;
        float4 v = W4[i];
        unsigned* p = &ws[k * 136 + q * 4];
        p[0] = f2tf(v.x); p[1] = f2tf(v.y); p[2] = f2tf(v.z); p[3] = f2tf(v.w);
    }
    #pragma unroll
    for (int i = tid; i < 2048; i += 256) {
        int r = i >> 4, q = i & 15;
        int gr = row0 + r;
        float2 f0 = {0, 0}, f1 = {0, 0};
        if (gr < NN) {
            uint2 u = a8[gr * 16 + q];
            f0 = __half22float2(*(const __half2*)&u.x);
            f1 = __half22float2(*(const __half2*)&u.y);
        }
        unsigned* p = &xs[r * 68 + q * 4];
        p[0] = f2tf(f0.x); p[1] = f2tf(f0.y); p[2] = f2tf(f1.x); p[3] = f2tf(f1.y);
    }
    __syncthreads();

    int warp = tid >> 5, lane = tid & 31;
    int gid = lane >> 2, tig = lane & 3;
    int wr = warp * 16;
    float acc[16][4];
    #pragma unroll
    for (int nt = 0; nt < 16; nt++)
        #pragma unroll
        for (int j = 0; j < 4; j++) acc[nt][j] = 0.f;

    #pragma unroll 2
    for (int ks = 0; ks < 8; ks++) {
        int k0 = ks * 8;
        unsigned a[4];
        a[0] = xs[(wr + gid) * 68 + k0 + tig];
        a[1] = xs[(wr + gid + 8) * 68 + k0 + tig];
        a[2] = xs[(wr + gid) * 68 + k0 + tig + 4];
        a[3] = xs[(wr + gid + 8) * 68 + k0 + tig + 4];
        #pragma unroll
        for (int nt = 0; nt < 16; nt++) {
            unsigned b0 = ws[(k0 + tig) * 136 + nt * 8 + gid];
            unsigned b1 = ws[(k0 + tig + 4) * 136 + nt * 8 + gid];
            mma_tf32(acc[nt], a, b0, b1);
        }
    }

    int r0 = row0 + wr + gid;
    int r1 = r0 + 8;
    float2* o2 = (float2*)out;
    #pragma unroll
    for (int nt = 0; nt < 16; nt++) {
        int col = nt * 8 + 2 * tig;
        float bx = __ldg(&b2[col]), by = __ldg(&b2[col + 1]);
        int c2i = col >> 1;
        if (r0 < NN) o2[r0 * 64 + c2i] = make_float2(acc[nt][0] + bx, acc[nt][1] + by);
        if (r1 < NN) o2[r1 * 64 + c2i] = make_float2(acc[nt][2] + bx, acc[nt][3] + by);
    }
}

extern "C" void kernel_launch(void* const* d_in, const int* in_sizes, int n_in,
                              void* d_out, int out_size) {
    const float* x  = (const float*)d_in[0];
    const int*   ei = (const int*)d_in[1];   // [2, E] int32
    const float* W1 = (const float*)d_in[2];
    const float* b1 = (const float*)d_in[3];
    const float* W2 = (const float*)d_in[4];
    const float* b2 = (const float*)d_in[5];
    float* out = (float*)d_out;

    const int* src = ei;
    const int* dst = ei + NE;

    static cudaStream_t s2 = nullptr;
    static cudaEvent_t e_fork = nullptr, e_join = nullptr;
    if (!s2) {
        cudaStreamCreateWithFlags(&s2, cudaStreamNonBlocking);
        cudaEventCreateWithFlags(&e_fork, cudaEventDisableTiming);
        cudaEventCreateWithFlags(&e_join, cudaEventDisableTiming);
    }

    // Fork: gemm1 runs parallel to CSR build.
    cudaEventRecord(e_fork, 0);
    cudaStreamWaitEvent(s2, e_fork, 0);
    k_gemm1<<<(NN + 127) / 128, 256, 0, s2>>>(x, W1);
    cudaEventRecord(e_join, s2);

    // CSR build on the main (capture) stream.
    k_zero   <<<(NN + 255) / 256, 256>>>();
    k_count  <<<(NE + 255) / 256, 256>>>(dst);
    k_scan1  <<<NB_SCAN, 256>>>();
    k_scan3  <<<(NN + 255) / 256, 256>>>();
    k_fillcsr<<<(NE + 255) / 256, 256>>>(src, dst);

    cudaStreamWaitEvent(0, e_join, 0);
    k_aggcsr<1><<<(NN * 8 + 255) / 256, 256>>>(b1);
    k_aggcsr<2><<<(NN * 8 + 255) / 256, 256>>>(b1);
    k_gemm2    <<<(NN + 127) / 128, 256>>>(W2, b2, out);
}